// round 13
// baseline (speedup 1.0000x reference)
#include <cuda_runtime.h>
#include <cuda_bf16.h>
#include <float.h>
#include <math.h>
#include <stdint.h>

// Problem constants
#define B 64
#define IN_DIM 256
#define H 512
#define M 64
#define N 8192
#define GJ 2048          // 4*H
#define KPART 768        // inp + h K-columns
#define DTILE 128        // rows per Mem tile (64 tiles per batch)

// Dynamic shared arena: 10240 floats = 40KB
//  tile/A region: [0, 8192)
//  aux region:    [8192, 10240)
#define SDYN_BYTES 40960

// Output layout (floats)
#define OUT_C_OFF (B*H)
#define OUT_R_OFF (2*B*H)
#define OUT_W_OFF (2*B*H + B*N)
#define OUT_M_OFF (2*B*H + 2*B*N)

// Scratch (static device globals — no allocation)
__device__ float g_k[B*M];
__device__ __align__(128) float g_par[B*32];
__device__ float g_logit[B*N];
__device__ float g_mpart[B*64*M];
__device__ float g_gatesT[GJ*B];              // partial gates [j][b]
__device__ float g_ea[B*2*M];

// Flags (zero-init). Lifecycle: set+used in one launch, reset one launch later.
__device__ int fA[B];   // set+used K1 -> reset K2
__device__ int fB[B];   // set+used K2 -> reset K3
__device__ int fC[B];   // set+used K3 -> reset K4
__device__ int fD[B];   // set+used K4 -> reset K1 (next replay)

__device__ __forceinline__ float sigf(float x) { return 1.0f / (1.0f + __expf(-x)); }

__device__ __forceinline__ void spin_on(int* f)
{
    if (threadIdx.x == 0) {
        while (atomicAdd(f, 0) == 0) __nanosleep(64);
    }
    __syncthreads();
    __threadfence();
}

__device__ __forceinline__ void release(int* f)
{
    __threadfence();
    __syncthreads();
    if (threadIdx.x == 0) atomicExch(f, 1);
}

// ---------------------------------------------------------------------------
// Async-stage a contiguous 32KB Mem tile into shared (zero register cost).
// 256 threads x 8 x 16B (cp.async.cg bypasses L1).
// ---------------------------------------------------------------------------
__device__ __forceinline__ void stage_tile(float* tilebuf, const float* gbase)
{
    unsigned int t = threadIdx.x;
    unsigned int s = (unsigned int)__cvta_generic_to_shared(tilebuf) + t * 16u;
    const char* g = (const char*)gbase + (size_t)t * 16;
    #pragma unroll
    for (int i = 0; i < 8; i++)
        asm volatile("cp.async.cg.shared.global [%0], [%1], 16;"
                     :: "r"(s + i*4096u), "l"(g + (size_t)i*4096) : "memory");
    asm volatile("cp.async.commit_group;" ::: "memory");
}

__device__ __forceinline__ void wait_tile()
{
    asm volatile("cp.async.wait_group 0;" ::: "memory");
    __syncthreads();
}

// ---------------------------------------------------------------------------
// Block reductions (256 threads, 8 warps); red = 8-float scratch
// ---------------------------------------------------------------------------
__device__ __forceinline__ float bsum(float v, float* red)
{
    #pragma unroll
    for (int o = 16; o; o >>= 1) v += __shfl_xor_sync(0xffffffffu, v, o);
    int t = threadIdx.x;
    if ((t & 31) == 0) red[t >> 5] = v;
    __syncthreads();
    if (t < 8) {
        v = red[t];
        #pragma unroll
        for (int o = 4; o; o >>= 1) v += __shfl_xor_sync(0xffu, v, o);
        if (t == 0) red[0] = v;
    }
    __syncthreads();
    float r = red[0];
    __syncthreads();
    return r;
}

__device__ __forceinline__ float bmax(float v, float* red)
{
    #pragma unroll
    for (int o = 16; o; o >>= 1) v = fmaxf(v, __shfl_xor_sync(0xffffffffu, v, o));
    int t = threadIdx.x;
    if ((t & 31) == 0) red[t >> 5] = v;
    __syncthreads();
    if (t < 8) {
        v = red[t];
        #pragma unroll
        for (int o = 4; o; o >>= 1) v = fmaxf(v, __shfl_xor_sync(0xffu, v, o));
        if (t == 0) red[0] = v;
    }
    __syncthreads();
    float r = red[0];
    __syncthreads();
    return r;
}

// ---------------------------------------------------------------------------
// Controller core: hs in shared; scratch = 128 floats shared.
// ---------------------------------------------------------------------------
__device__ void controller_core(int b, const float* hs, float* scratch,
                                const float* __restrict__ kw, const float* __restrict__ kb,
                                const float* __restrict__ cw, const float* __restrict__ cb,
                                const float* __restrict__ sw, const float* __restrict__ sb,
                                const float* __restrict__ ww, const float* __restrict__ wb)
{
    int t = threadIdx.x;
    float* ks  = scratch;        // 64
    float* cvs = scratch + 64;   // 3
    float* ss  = scratch + 70;   // 3

    if (t < M) {
        const float4* w4 = (const float4*)(kw + (size_t)t * H);
        float acc = kb[t];
        #pragma unroll 8
        for (int q = 0; q < H/4; q++) {
            float4 wv = w4[q]; int j = q*4;
            acc += wv.x*hs[j] + wv.y*hs[j+1] + wv.z*hs[j+2] + wv.w*hs[j+3];
        }
        ks[t] = tanhf(acc);
    } else if (t < M + 3) {
        int r = t - M;
        const float4* w4 = (const float4*)(cw + (size_t)r * H);
        float acc = cb[r];
        for (int q = 0; q < H/4; q++) {
            float4 wv = w4[q]; int j = q*4;
            acc += wv.x*hs[j] + wv.y*hs[j+1] + wv.z*hs[j+2] + wv.w*hs[j+3];
        }
        cvs[r] = acc;
    } else if (t < M + 6) {
        int r = t - M - 3;
        const float4* w4 = (const float4*)(sw + (size_t)r * H);
        float acc = sb[r];
        for (int q = 0; q < H/4; q++) {
            float4 wv = w4[q]; int j = q*4;
            acc += wv.x*hs[j] + wv.y*hs[j+1] + wv.z*hs[j+2] + wv.w*hs[j+3];
        }
        ss[r] = acc;
    } else if (ww != nullptr && t >= 70 && t < 70 + 2*M) {
        int r = t - 70;
        const float4* w4 = (const float4*)(ww + (size_t)r * H);
        float acc = wb[r];
        for (int q = 0; q < H/4; q++) {
            float4 wv = w4[q]; int j = q*4;
            acc += wv.x*hs[j] + wv.y*hs[j+1] + wv.z*hs[j+2] + wv.w*hs[j+3];
        }
        g_ea[b*2*M + r] = (r < M) ? sigf(acc) : acc;
    }
    __syncthreads();

    if (t < M) g_k[b*M + t] = ks[t];
    if (t == 0) {
        float mx = fmaxf(ss[0], fmaxf(ss[1], ss[2]));
        float e0 = __expf(ss[0]-mx), e1 = __expf(ss[1]-mx), e2 = __expf(ss[2]-mx);
        float tot = e0 + e1 + e2;
        float nk = 0.0f;
        for (int j = 0; j < M; j++) nk += ks[j]*ks[j];
        g_par[b*32 + 0] = fmaxf(cvs[0], 0.0f) + 0.0001f;
        g_par[b*32 + 1] = sigf(cvs[1]);
        g_par[b*32 + 2] = fmaxf(cvs[2], 0.0f) + 1.0001f;
        g_par[b*32 + 3] = e0/tot;
        g_par[b*32 + 4] = e1/tot;
        g_par[b*32 + 5] = e2/tot;
        g_par[b*32 + 6] = nk;
    }
}

__device__ void controller_load(int b, const float* __restrict__ hstate, float* sdyn,
                                const float* kw, const float* kb,
                                const float* cw, const float* cb,
                                const float* sw, const float* sb,
                                const float* ww, const float* wb)
{
    float* hs = sdyn;                 // 512
    int t = threadIdx.x;
    for (int i = t; i < H; i += 256) hs[i] = hstate[(size_t)b*H + i];
    __syncthreads();
    controller_core(b, hs, sdyn + 512, kw, kb, cw, cb, sw, sb, ww, wb);
}

// ---------------------------------------------------------------------------
// GEMM-partial: gatesT[j][b] = bias_j + inp[b]@W_ih[j,:256] + h[b]@W_hh[j,:]
// Xs = sdyn[0,2112), Ws = sdyn[2112,3168)   ([64][33] / [32][33])
// ---------------------------------------------------------------------------
__device__ void gemm_partial(int gbid, float* sdyn,
                             const float* __restrict__ inp,
                             const float* __restrict__ h,
                             const float* __restrict__ W_ih,
                             const float* __restrict__ b_ih,
                             const float* __restrict__ W_hh,
                             const float* __restrict__ b_hh)
{
    float* Xs = sdyn;            // [64][33]
    float* Ws = sdyn + 2112;     // [32][33]
    int t  = threadIdx.x;
    int tx = t & 15;
    int ty = t >> 4;
    int jbase = gbid * 32;
    int lrow = t >> 2;
    int lcol = (t & 3) * 8;
    int wrow = t >> 3;
    int wcol = (t & 7) * 4;

    float acc[4][2];
    #pragma unroll
    for (int i = 0; i < 4; i++) { acc[i][0] = 0.0f; acc[i][1] = 0.0f; }

    for (int kc = 0; kc < KPART/32; kc++) {
        int k0 = kc * 32;
        const float* xsrc = (k0 < IN_DIM)
            ? (inp + (size_t)lrow*IN_DIM + k0 + lcol)
            : (h   + (size_t)lrow*H + (k0 - IN_DIM) + lcol);
        float4 xa = *(const float4*)xsrc;
        float4 xb = *(const float4*)(xsrc + 4);
        float* xr = Xs + lrow*33 + lcol;
        xr[0]=xa.x; xr[1]=xa.y; xr[2]=xa.z; xr[3]=xa.w;
        xr[4]=xb.x; xr[5]=xb.y; xr[6]=xb.z; xr[7]=xb.w;
        const float* wsrc = (k0 < IN_DIM)
            ? (W_ih + (size_t)(jbase + wrow)*(IN_DIM + M) + k0 + wcol)
            : (W_hh + (size_t)(jbase + wrow)*H + (k0 - IN_DIM) + wcol);
        float4 wa = *(const float4*)wsrc;
        float* wr = Ws + wrow*33 + wcol;
        wr[0]=wa.x; wr[1]=wa.y; wr[2]=wa.z; wr[3]=wa.w;
        __syncthreads();
        #pragma unroll
        for (int k = 0; k < 32; k++) {
            float xv[4], wv[2];
            #pragma unroll
            for (int i = 0; i < 4; i++) xv[i] = Xs[(tx*4 + i)*33 + k];
            wv[0] = Ws[(ty*2 + 0)*33 + k];
            wv[1] = Ws[(ty*2 + 1)*33 + k];
            #pragma unroll
            for (int i = 0; i < 4; i++) {
                acc[i][0] += xv[i] * wv[0];
                acc[i][1] += xv[i] * wv[1];
            }
        }
        __syncthreads();
    }
    #pragma unroll
    for (int jj = 0; jj < 2; jj++) {
        int j = jbase + ty*2 + jj;
        float bias = b_ih[j] + b_hh[j];
        #pragma unroll
        for (int i = 0; i < 4; i++)
            g_gatesT[(size_t)j*B + (tx*4 + i)] = acc[i][jj] + bias;
    }
}

// ---------------------------------------------------------------------------
// Dot tile: cp.async stage -> spin -> consume from smem -> logits.
// ---------------------------------------------------------------------------
__device__ void dot_tile(const float* __restrict__ Mem, int b, int xt,
                         int* flags, float* sdyn)
{
    int t = threadIdx.x;
    int lane8 = t & 7, rowp = t >> 3;
    size_t base = ((size_t)b*N + xt*DTILE)*M;
    float* tile = sdyn;

    stage_tile(tile, Mem + base);
    spin_on(&flags[b]);
    wait_tile();

    int m0 = lane8 * 8;
    float4 ka = *(const float4*)(g_k + b*M + m0);
    float4 kb4 = *(const float4*)(g_k + b*M + m0 + 4);
    float beta = g_par[b*32 + 0];
    float nk   = g_par[b*32 + 6];

    #pragma unroll
    for (int it = 0; it < 4; it++) {
        int row = it*32 + rowp;
        const float4* p = (const float4*)(tile + row*M) + lane8*2;
        float4 v0 = p[0], v1 = p[1];
        float d  = v0.x*ka.x + v0.y*ka.y + v0.z*ka.z + v0.w*ka.w
                 + v1.x*kb4.x + v1.y*kb4.y + v1.z*kb4.z + v1.w*kb4.w;
        float nm = v0.x*v0.x + v0.y*v0.y + v0.z*v0.z + v0.w*v0.w
                 + v1.x*v1.x + v1.y*v1.y + v1.z*v1.z + v1.w*v1.w;
        #pragma unroll
        for (int o = 4; o; o >>= 1) {
            d  += __shfl_xor_sync(0xffffffffu, d,  o);
            nm += __shfl_xor_sync(0xffffffffu, nm, o);
        }
        if (lane8 == 0) g_logit[(size_t)b*N + xt*DTILE + row] = beta * d / (nm * nk);
    }
}

// ---------------------------------------------------------------------------
// Address: A = sdyn[0,8192), red = sdyn[8192,8200)
// ---------------------------------------------------------------------------
__device__ void address_dev(int b, const float* __restrict__ head_prev,
                            float* __restrict__ out_head, float* sdyn)
{
    float* A   = sdyn;
    float* red = sdyn + 8192;
    int t = threadIdx.x;
    float g     = g_par[b*32 + 1];
    float gamma = g_par[b*32 + 2];
    float s0    = g_par[b*32 + 3];
    float s1    = g_par[b*32 + 4];
    float s2    = g_par[b*32 + 5];

    const float* lg = g_logit + (size_t)b*N;
    float vmax = -FLT_MAX;
    #pragma unroll
    for (int i = 0; i < 32; i++) {
        float v = lg[i*256 + t];
        A[i*256 + t] = v;
        vmax = fmaxf(vmax, v);
    }
    vmax = bmax(vmax, red);

    float lsum = 0.0f;
    #pragma unroll
    for (int i = 0; i < 32; i++) {
        int idx = i*256 + t;
        float e = __expf(A[idx] - vmax);
        A[idx] = e;
        lsum += e;
    }
    float inv = 1.0f / bsum(lsum, red);

    const float* hp = head_prev + (size_t)b*N;
    #pragma unroll
    for (int i = 0; i < 32; i++) {
        int idx = i*256 + t;
        A[idx] = g * (A[idx] * inv) + (1.0f - g) * hp[idx];
    }
    __syncthreads();

    float p[32];
    float psum = 0.0f;
    #pragma unroll
    for (int i = 0; i < 32; i++) {
        int idx = i*256 + t;
        float o = s0 * A[(idx + N - 2) & (N-1)]
                + s1 * A[(idx + N - 1) & (N-1)]
                + s2 * A[idx];
        p[i] = __powf(o, gamma);
        psum += p[i];
    }
    float inv2 = 1.0f / bsum(psum, red);
    #pragma unroll
    for (int i = 0; i < 32; i++)
        out_head[(size_t)b*N + i*256 + t] = p[i] * inv2;
}

// ---------------------------------------------------------------------------
// M_read tile: stage -> spin fB -> weighted sum from smem -> write partial.
// tile = sdyn[0,8192), sdata = sdyn[8192,10240)
// ---------------------------------------------------------------------------
__device__ void mread_tile(const float* __restrict__ Mem,
                           const float* __restrict__ rhead, int b, int xt,
                           float* sdyn)
{
    int t = threadIdx.x;
    int lane8 = t & 7, rowp = t >> 3;
    size_t base = ((size_t)b*N + xt*DTILE)*M;
    float* tile  = sdyn;
    float* sdata = sdyn + 8192;

    stage_tile(tile, Mem + base);
    spin_on(&fB[b]);
    wait_tile();

    float a0=0,a1=0,a2=0,a3=0,a4=0,a5=0,a6=0,a7=0;
    const float* hp = rhead + (size_t)b*N + xt*DTILE;
    #pragma unroll
    for (int it = 0; it < 4; it++) {
        int row = it*32 + rowp;
        float r = hp[row];
        const float4* p = (const float4*)(tile + row*M) + lane8*2;
        float4 v0 = p[0], v1 = p[1];
        a0 += r*v0.x; a1 += r*v0.y; a2 += r*v0.z; a3 += r*v0.w;
        a4 += r*v1.x; a5 += r*v1.y; a6 += r*v1.z; a7 += r*v1.w;
    }

    float* s = sdata + t*8;
    s[0]=a0; s[1]=a1; s[2]=a2; s[3]=a3; s[4]=a4; s[5]=a5; s[6]=a6; s[7]=a7;
    __syncthreads();
    if (t < 64) {
        int lg2 = t >> 3, j = t & 7;
        float acc = 0.0f;
        #pragma unroll
        for (int rw = 0; rw < 32; rw++) acc += sdata[((rw<<3) | lg2)*8 + j];
        g_mpart[((size_t)b*64 + xt)*M + lg2*8 + j] = acc;
    }
}

// ---------------------------------------------------------------------------
// fc: per-batch fused [partial-reduce -> gates fixup -> LSTM -> write ctrl].
// mr = sdyn[0,64), hs = sdyn[64,576), sr = sdyn[576,832), ctrl scratch +832.
// ---------------------------------------------------------------------------
__device__ void fc_dev(int b, float* sdyn, const float* __restrict__ W_ih,
                       const float* __restrict__ c,
                       float* __restrict__ out_h, float* __restrict__ out_c,
                       const float* kw, const float* kb,
                       const float* cw, const float* cb,
                       const float* sw, const float* sb,
                       const float* ww, const float* wb)
{
    int t = threadIdx.x;
    float* mr = sdyn;
    float* hs = sdyn + 64;
    float* sr = sdyn + 576;

    // reduce 64 partial chunks -> M_read[b]
    {
        int m = t & 63, q = t >> 6;
        float a = 0.0f;
        #pragma unroll
        for (int p = 0; p < 16; p++)
            a += g_mpart[((size_t)b*64 + q*16 + p)*M + m];
        sr[t] = a;
        __syncthreads();
        if (t < 64) mr[t] = sr[t] + sr[64+t] + sr[128+t] + sr[192+t];
        __syncthreads();
    }

    // gates fixup + LSTM cell: thread handles h = t and t+256
    #pragma unroll
    for (int i = 0; i < 2; i++) {
        int hh = t + i*256;
        float gv[4];
        #pragma unroll
        for (int gg = 0; gg < 4; gg++) {
            int j = gg*H + hh;
            float acc = g_gatesT[(size_t)j*B + b];
            const float4* w4 = (const float4*)(W_ih + (size_t)j*(IN_DIM + M) + IN_DIM);
            #pragma unroll
            for (int q = 0; q < 16; q++) {
                float4 wv = w4[q];
                acc += wv.x*mr[q*4+0] + wv.y*mr[q*4+1] + wv.z*mr[q*4+2] + wv.w*mr[q*4+3];
            }
            gv[gg] = acc;
        }
        float cn = sigf(gv[1]) * c[(size_t)b*H + hh] + sigf(gv[0]) * tanhf(gv[2]);
        float hn = sigf(gv[3]) * tanhf(cn);
        out_c[(size_t)b*H + hh] = cn;
        out_h[(size_t)b*H + hh] = hn;
        hs[hh] = hn;
    }
    __syncthreads();

    controller_core(b, hs, sdyn + 832, kw, kb, cw, cb, sw, sb, ww, wb);
}

// ---------------------------------------------------------------------------
// M_out tile: stage -> spin fD -> update from smem (streaming stores)
// ---------------------------------------------------------------------------
__device__ void mout_tile(const float* __restrict__ Mem,
                          const float* __restrict__ whead,
                          float* __restrict__ outM, int b, int xt, float* sdyn)
{
    int t = threadIdx.x;
    int lane8 = t & 7, rowp = t >> 3;
    size_t base = ((size_t)b*N + xt*DTILE)*M;
    float* tile = sdyn;

    stage_tile(tile, Mem + base);
    spin_on(&fD[b]);
    wait_tile();

    int m0 = lane8 * 8;
    float4 e0v = *(const float4*)(g_ea + b*2*M + m0);
    float4 e1v = *(const float4*)(g_ea + b*2*M + m0 + 4);
    float4 a0v = *(const float4*)(g_ea + b*2*M + M + m0);
    float4 a1v = *(const float4*)(g_ea + b*2*M + M + m0 + 4);

    #pragma unroll
    for (int it = 0; it < 4; it++) {
        int row = it*32 + rowp;
        float w = whead[(size_t)b*N + xt*DTILE + row];
        const float4* p = (const float4*)(tile + row*M) + lane8*2;
        float4 v0 = p[0], v1 = p[1];
        float4 o0, o1;
        o0.x = v0.x*(1.0f - w*e0v.x) + w*a0v.x;
        o0.y = v0.y*(1.0f - w*e0v.y) + w*a0v.y;
        o0.z = v0.z*(1.0f - w*e0v.z) + w*a0v.z;
        o0.w = v0.w*(1.0f - w*e0v.w) + w*a0v.w;
        o1.x = v1.x*(1.0f - w*e1v.x) + w*a1v.x;
        o1.y = v1.y*(1.0f - w*e1v.y) + w*a1v.y;
        o1.z = v1.z*(1.0f - w*e1v.z) + w*a1v.z;
        o1.w = v1.w*(1.0f - w*e1v.w) + w*a1v.w;
        float4* q = (float4*)(outM + base + (size_t)row*M) + lane8*2;
        __stcs(q,     o0);
        __stcs(q + 1, o1);
    }
}

// ===========================================================================
// K1: ctrl(read) [0,64) | gemm [64,128) | dotR FWD [128, 128+4096)
// ===========================================================================
__global__ void __launch_bounds__(256, 5) k1_kernel(
    const float* __restrict__ Mem, const float* __restrict__ inp,
    const float* __restrict__ h,
    const float* __restrict__ W_ih, const float* __restrict__ b_ih,
    const float* __restrict__ W_hh, const float* __restrict__ b_hh,
    const float* __restrict__ rk_w, const float* __restrict__ rk_b,
    const float* __restrict__ rc_w, const float* __restrict__ rc_b,
    const float* __restrict__ rs_w, const float* __restrict__ rs_b)
{
    extern __shared__ float sdyn[];
    int bid = blockIdx.x;
    if (bid < B) {
        if (threadIdx.x == 0) fD[bid] = 0;   // reset K4 flags (prev replay)
        controller_load(bid, h, sdyn, rk_w, rk_b, rc_w, rc_b, rs_w, rs_b,
                        nullptr, nullptr);
        release(&fA[bid]);
        return;
    }
    if (bid < 2*B) {
        gemm_partial(bid - B, sdyn, inp, h, W_ih, b_ih, W_hh, b_hh);
        return;
    }
    int idx = bid - 2*B;
    dot_tile(Mem, idx >> 6, idx & 63, fA, sdyn);    // forward
}

// ===========================================================================
// K2: addrR [0,64) | mread REV [64, 64+4096)
// ===========================================================================
__global__ void __launch_bounds__(256, 5) k2_kernel(
    const float* __restrict__ Mem,
    const float* __restrict__ rhead, float* __restrict__ out_r)
{
    extern __shared__ float sdyn[];
    int bid = blockIdx.x;
    if (bid < B) {
        if (threadIdx.x == 0) fA[bid] = 0;   // reset K1 flags
        address_dev(bid, rhead, out_r, sdyn);
        release(&fB[bid]);
        return;
    }
    int idx = bid - B;
    int b  = B - 1 - (idx >> 6);             // reversed (serpentine after K1 fwd)
    int xt = 63 - (idx & 63);
    mread_tile(Mem, out_r, b, xt, sdyn);
}

// ===========================================================================
// K3: fc [0,64) | dotW FWD [64, 64+4096)
// ===========================================================================
__global__ void __launch_bounds__(256, 5) k3_kernel(
    const float* __restrict__ Mem,
    const float* __restrict__ W_ih, const float* __restrict__ c,
    float* __restrict__ out_h, float* __restrict__ out_c,
    const float* __restrict__ wk_w, const float* __restrict__ wk_b,
    const float* __restrict__ wc_w, const float* __restrict__ wc_b,
    const float* __restrict__ ws_w, const float* __restrict__ ws_b,
    const float* __restrict__ w_w,  const float* __restrict__ w_b)
{
    extern __shared__ float sdyn[];
    int bid = blockIdx.x;
    if (bid < B) {
        if (threadIdx.x == 0) fB[bid] = 0;   // reset K2 flags
        fc_dev(bid, sdyn, W_ih, c, out_h, out_c,
               wk_w, wk_b, wc_w, wc_b, ws_w, ws_b, w_w, w_b);
        release(&fC[bid]);
        return;
    }
    int idx = bid - B;
    dot_tile(Mem, idx >> 6, idx & 63, fC, sdyn);   // forward
}

// ===========================================================================
// K4: addrW [0,64) | mout REV [64, 64+4096)
// ===========================================================================
__global__ void __launch_bounds__(256, 5) k4_kernel(
    const float* __restrict__ Mem, const float* __restrict__ whead,
    float* __restrict__ out_w, float* __restrict__ out_m)
{
    extern __shared__ float sdyn[];
    int bid = blockIdx.x;
    if (bid < B) {
        if (threadIdx.x == 0) fC[bid] = 0;   // reset K3 flags
        address_dev(bid, whead, out_w, sdyn);
        release(&fD[bid]);
        return;
    }
    int idx = bid - B;
    int b  = B - 1 - (idx >> 6);             // reversed (serpentine after K3 fwd)
    int xt = 63 - (idx & 63);
    mout_tile(Mem, out_w, out_m, b, xt, sdyn);
}

// ---------------------------------------------------------------------------
extern "C" void kernel_launch(void* const* d_in, const int* in_sizes, int n_in,
                              void* d_out, int out_size)
{
    const float* inp    = (const float*)d_in[0];
    const float* h      = (const float*)d_in[1];
    const float* c      = (const float*)d_in[2];
    const float* rhead  = (const float*)d_in[3];
    const float* whead  = (const float*)d_in[4];
    const float* mem    = (const float*)d_in[5];
    const float* W_ih   = (const float*)d_in[6];
    const float* b_ih   = (const float*)d_in[7];
    const float* W_hh   = (const float*)d_in[8];
    const float* b_hh   = (const float*)d_in[9];
    const float* rk_w   = (const float*)d_in[10];
    const float* rk_b   = (const float*)d_in[11];
    const float* rc_w   = (const float*)d_in[12];
    const float* rc_b   = (const float*)d_in[13];
    const float* rs_w   = (const float*)d_in[14];
    const float* rs_b   = (const float*)d_in[15];
    const float* wk_w   = (const float*)d_in[16];
    const float* wk_b   = (const float*)d_in[17];
    const float* wc_w   = (const float*)d_in[18];
    const float* wc_b   = (const float*)d_in[19];
    const float* ws_w   = (const float*)d_in[20];
    const float* ws_b   = (const float*)d_in[21];
    const float* w_w    = (const float*)d_in[22];
    const float* w_b    = (const float*)d_in[23];

    float* out   = (float*)d_out;
    float* out_h = out;
    float* out_c = out + OUT_C_OFF;
    float* out_r = out + OUT_R_OFF;
    float* out_w = out + OUT_W_OFF;
    float* out_m = out + OUT_M_OFF;

    k1_kernel<<<2*B + 4096, 256, SDYN_BYTES>>>(mem, inp, h, W_ih, b_ih, W_hh, b_hh,
                                               rk_w, rk_b, rc_w, rc_b, rs_w, rs_b);
    k2_kernel<<<B + 4096, 256, SDYN_BYTES>>>(mem, rhead, out_r);
    k3_kernel<<<B + 4096, 256, SDYN_BYTES>>>(mem, W_ih, c, out_h, out_c,
                                             wk_w, wk_b, wc_w, wc_b, ws_w, ws_b,
                                             w_w, w_b);
    k4_kernel<<<B + 4096, 256, SDYN_BYTES>>>(mem, whead, out_w, out_m);
}

// round 14
// speedup vs baseline: 1.1865x; 1.1865x over previous
#include <cuda_runtime.h>
#include <cuda_bf16.h>
#include <float.h>
#include <math.h>

// Problem constants
#define B 64
#define IN_DIM 256
#define H 512
#define M 64
#define N 8192
#define GJ 2048          // 4*H
#define KPART 768        // inp + h K-columns
#define NCHUNK 16        // mread chunks (512 rows each)

// Output layout (floats)
#define OUT_C_OFF (B*H)
#define OUT_R_OFF (2*B*H)
#define OUT_W_OFF (2*B*H + B*N)
#define OUT_M_OFF (2*B*H + 2*B*N)

// Scratch (static device globals — no allocation)
__device__ float g_k[B*M];
__device__ __align__(128) float g_par[B*32];
__device__ float g_logit[B*N];
__device__ float g_mpart[B*NCHUNK*M];
__device__ float g_gatesT[GJ*B];     // partial gates, transposed [j][b]
__device__ float g_ea[B*2*M];

__device__ __forceinline__ float sigf(float x) { return 1.0f / (1.0f + __expf(-x)); }

// ---------------------------------------------------------------------------
// Controller core: hs (h state) in shared memory. 256 threads.
// ---------------------------------------------------------------------------
__device__ void controller_core(int b, const float* hs,
                                const float* __restrict__ kw, const float* __restrict__ kb,
                                const float* __restrict__ cw, const float* __restrict__ cb,
                                const float* __restrict__ sw, const float* __restrict__ sb,
                                const float* __restrict__ ww, const float* __restrict__ wb)
{
    int t = threadIdx.x;
    __shared__ float ks[M];
    __shared__ float cvs[3];
    __shared__ float ss[3];

    if (t < M) {
        const float4* w4 = (const float4*)(kw + (size_t)t * H);
        float acc = kb[t];
        #pragma unroll 8
        for (int q = 0; q < H/4; q++) {
            float4 wv = w4[q]; int j = q*4;
            acc += wv.x*hs[j] + wv.y*hs[j+1] + wv.z*hs[j+2] + wv.w*hs[j+3];
        }
        ks[t] = tanhf(acc);
    } else if (t < M + 3) {
        int r = t - M;
        const float4* w4 = (const float4*)(cw + (size_t)r * H);
        float acc = cb[r];
        for (int q = 0; q < H/4; q++) {
            float4 wv = w4[q]; int j = q*4;
            acc += wv.x*hs[j] + wv.y*hs[j+1] + wv.z*hs[j+2] + wv.w*hs[j+3];
        }
        cvs[r] = acc;
    } else if (t < M + 6) {
        int r = t - M - 3;
        const float4* w4 = (const float4*)(sw + (size_t)r * H);
        float acc = sb[r];
        for (int q = 0; q < H/4; q++) {
            float4 wv = w4[q]; int j = q*4;
            acc += wv.x*hs[j] + wv.y*hs[j+1] + wv.z*hs[j+2] + wv.w*hs[j+3];
        }
        ss[r] = acc;
    } else if (ww != nullptr && t >= 70 && t < 70 + 2*M) {
        int r = t - 70;
        const float4* w4 = (const float4*)(ww + (size_t)r * H);
        float acc = wb[r];
        for (int q = 0; q < H/4; q++) {
            float4 wv = w4[q]; int j = q*4;
            acc += wv.x*hs[j] + wv.y*hs[j+1] + wv.z*hs[j+2] + wv.w*hs[j+3];
        }
        g_ea[b*2*M + r] = (r < M) ? sigf(acc) : acc;
    }
    __syncthreads();

    if (t < M) g_k[b*M + t] = ks[t];
    if (t == 0) {
        float mx = fmaxf(ss[0], fmaxf(ss[1], ss[2]));
        float e0 = __expf(ss[0]-mx), e1 = __expf(ss[1]-mx), e2 = __expf(ss[2]-mx);
        float tot = e0 + e1 + e2;
        float nk = 0.0f;
        for (int j = 0; j < M; j++) nk += ks[j]*ks[j];
        g_par[b*32 + 0] = fmaxf(cvs[0], 0.0f) + 0.0001f;
        g_par[b*32 + 1] = sigf(cvs[1]);
        g_par[b*32 + 2] = fmaxf(cvs[2], 0.0f) + 1.0001f;
        g_par[b*32 + 3] = e0/tot;
        g_par[b*32 + 4] = e1/tot;
        g_par[b*32 + 5] = e2/tot;
        g_par[b*32 + 6] = nk;
    }
}

// ===========================================================================
// L0: read controller (one block per batch)
// ===========================================================================
__global__ void ctrl_kernel(const float* __restrict__ h,
                            const float* __restrict__ kw, const float* __restrict__ kb,
                            const float* __restrict__ cw, const float* __restrict__ cb,
                            const float* __restrict__ sw, const float* __restrict__ sb)
{
    __shared__ float hs[H];
    int b = blockIdx.x, t = threadIdx.x;
    for (int i = t; i < H; i += 256) hs[i] = h[(size_t)b*H + i];
    __syncthreads();
    controller_core(b, hs, kw, kb, cw, cb, sw, sb, nullptr, nullptr);
}

// ---------------------------------------------------------------------------
// GEMM-partial: gatesT[j][b] = bias_j + inp[b]@W_ih[j,:256] + h[b]@W_hh[j,:]
// ---------------------------------------------------------------------------
__device__ void gemm_partial(int gbid,
                             const float* __restrict__ inp,
                             const float* __restrict__ h,
                             const float* __restrict__ W_ih,
                             const float* __restrict__ b_ih,
                             const float* __restrict__ W_hh,
                             const float* __restrict__ b_hh)
{
    __shared__ float Xs[64][33];
    __shared__ float Ws[32][33];
    int t  = threadIdx.x;
    int tx = t & 15;
    int ty = t >> 4;
    int jbase = gbid * 32;
    int lrow = t >> 2;
    int lcol = (t & 3) * 8;
    int wrow = t >> 3;
    int wcol = (t & 7) * 4;

    float acc[4][2];
    #pragma unroll
    for (int i = 0; i < 4; i++) { acc[i][0] = 0.0f; acc[i][1] = 0.0f; }

    for (int kc = 0; kc < KPART/32; kc++) {
        int k0 = kc * 32;
        const float* xsrc = (k0 < IN_DIM)
            ? (inp + (size_t)lrow*IN_DIM + k0 + lcol)
            : (h   + (size_t)lrow*H + (k0 - IN_DIM) + lcol);
        float4 xa = *(const float4*)xsrc;
        float4 xb = *(const float4*)(xsrc + 4);
        Xs[lrow][lcol+0]=xa.x; Xs[lrow][lcol+1]=xa.y; Xs[lrow][lcol+2]=xa.z; Xs[lrow][lcol+3]=xa.w;
        Xs[lrow][lcol+4]=xb.x; Xs[lrow][lcol+5]=xb.y; Xs[lrow][lcol+6]=xb.z; Xs[lrow][lcol+7]=xb.w;
        const float* wsrc = (k0 < IN_DIM)
            ? (W_ih + (size_t)(jbase + wrow)*(IN_DIM + M) + k0 + wcol)
            : (W_hh + (size_t)(jbase + wrow)*H + (k0 - IN_DIM) + wcol);
        float4 wa = *(const float4*)wsrc;
        Ws[wrow][wcol+0]=wa.x; Ws[wrow][wcol+1]=wa.y; Ws[wrow][wcol+2]=wa.z; Ws[wrow][wcol+3]=wa.w;
        __syncthreads();
        #pragma unroll
        for (int k = 0; k < 32; k++) {
            float xv[4], wv[2];
            #pragma unroll
            for (int i = 0; i < 4; i++) xv[i] = Xs[tx*4 + i][k];
            wv[0] = Ws[ty*2 + 0][k];
            wv[1] = Ws[ty*2 + 1][k];
            #pragma unroll
            for (int i = 0; i < 4; i++) {
                acc[i][0] += xv[i] * wv[0];
                acc[i][1] += xv[i] * wv[1];
            }
        }
        __syncthreads();
    }
    #pragma unroll
    for (int jj = 0; jj < 2; jj++) {
        int j = jbase + ty*2 + jj;
        float bias = b_ih[j] + b_hh[j];
        #pragma unroll
        for (int i = 0; i < 4; i++)
            g_gatesT[(size_t)j*B + (tx*4 + i)] = acc[i][jj] + bias;
    }
}

// ---------------------------------------------------------------------------
// Dot tile (256 rows): plain R3-style streaming, no spin.
// logit[b,n] = beta * (k . Mem[b,n,:]) / (|Mem[b,n,:]|^2 * nk)
// ---------------------------------------------------------------------------
__device__ void dot_body(const float* __restrict__ Mem, int b, int xt)
{
    int t = threadIdx.x;
    __shared__ float ks[M];
    if (t < M) ks[t] = g_k[b*M + t];
    __syncthreads();
    float beta = g_par[b*32 + 0];
    float nk   = g_par[b*32 + 6];
    int lane8 = t & 7;
    int rowp  = t >> 3;
    int m0 = lane8 * 8;
    float k0=ks[m0],k1=ks[m0+1],k2=ks[m0+2],k3=ks[m0+3];
    float k4=ks[m0+4],k5=ks[m0+5],k6=ks[m0+6],k7=ks[m0+7];
    #pragma unroll
    for (int it = 0; it < 8; it++) {
        int n = xt*256 + it*32 + rowp;
        const float4* p = (const float4*)(Mem + ((size_t)b*N + n)*M) + lane8*2;
        float4 v0 = p[0], v1 = p[1];
        float d  = v0.x*k0 + v0.y*k1 + v0.z*k2 + v0.w*k3
                 + v1.x*k4 + v1.y*k5 + v1.z*k6 + v1.w*k7;
        float nm = v0.x*v0.x + v0.y*v0.y + v0.z*v0.z + v0.w*v0.w
                 + v1.x*v1.x + v1.y*v1.y + v1.z*v1.z + v1.w*v1.w;
        #pragma unroll
        for (int o = 4; o; o >>= 1) {
            d  += __shfl_xor_sync(0xffffffffu, d,  o);
            nm += __shfl_xor_sync(0xffffffffu, nm, o);
        }
        if (lane8 == 0) g_logit[(size_t)b*N + n] = beta * d / (nm * nk);
    }
}

// ===========================================================================
// L1: gemm [0,64) | dotR FWD [64, 64+2048)
// ===========================================================================
__global__ void dotg_kernel(const float* __restrict__ Mem,
                            const float* __restrict__ inp, const float* __restrict__ h,
                            const float* __restrict__ W_ih, const float* __restrict__ b_ih,
                            const float* __restrict__ W_hh, const float* __restrict__ b_hh)
{
    int bid = blockIdx.x;
    if (bid < 64) {
        gemm_partial(bid, inp, h, W_ih, b_ih, W_hh, b_hh);
        return;
    }
    int tile = bid - 64;
    dot_body(Mem, tile >> 5, tile & 31);
}

// ===========================================================================
// L5: dotW FWD (no gemm)
// ===========================================================================
__global__ void dotw_kernel(const float* __restrict__ Mem)
{
    int tile = blockIdx.x;
    dot_body(Mem, tile >> 5, tile & 31);
}

// ===========================================================================
// Address: 1024 threads, one block per batch (R3-proven version).
// ===========================================================================
__device__ __forceinline__ float bsum1k(float v, float* red)
{
    #pragma unroll
    for (int o = 16; o; o >>= 1) v += __shfl_xor_sync(0xffffffffu, v, o);
    int w = threadIdx.x >> 5, lane = threadIdx.x & 31;
    if (lane == 0) red[w] = v;
    __syncthreads();
    if (w == 0) {
        v = red[lane];
        #pragma unroll
        for (int o = 16; o; o >>= 1) v += __shfl_xor_sync(0xffffffffu, v, o);
        if (lane == 0) red[0] = v;
    }
    __syncthreads();
    float r = red[0];
    __syncthreads();
    return r;
}

__device__ __forceinline__ float bmax1k(float v, float* red)
{
    #pragma unroll
    for (int o = 16; o; o >>= 1) v = fmaxf(v, __shfl_xor_sync(0xffffffffu, v, o));
    int w = threadIdx.x >> 5, lane = threadIdx.x & 31;
    if (lane == 0) red[w] = v;
    __syncthreads();
    if (w == 0) {
        v = red[lane];
        #pragma unroll
        for (int o = 16; o; o >>= 1) v = fmaxf(v, __shfl_xor_sync(0xffffffffu, v, o));
        if (lane == 0) red[0] = v;
    }
    __syncthreads();
    float r = red[0];
    __syncthreads();
    return r;
}

__global__ void address_kernel(const float* __restrict__ head_prev,
                               float* __restrict__ out_head)
{
    int b = blockIdx.x, t = threadIdx.x;
    __shared__ float buf[N];
    __shared__ float red[32];
    float g     = g_par[b*32 + 1];
    float gamma = g_par[b*32 + 2];
    float s0    = g_par[b*32 + 3];
    float s1    = g_par[b*32 + 4];
    float s2    = g_par[b*32 + 5];

    const float* lg = g_logit + (size_t)b*N;
    float l[8];
    float vmax = -FLT_MAX;
    #pragma unroll
    for (int i = 0; i < 8; i++) { l[i] = lg[i*1024 + t]; vmax = fmaxf(vmax, l[i]); }
    vmax = bmax1k(vmax, red);

    float lsum = 0.0f;
    #pragma unroll
    for (int i = 0; i < 8; i++) { l[i] = __expf(l[i] - vmax); lsum += l[i]; }
    float inv = 1.0f / bsum1k(lsum, red);

    const float* hp = head_prev + (size_t)b*N;
    #pragma unroll
    for (int i = 0; i < 8; i++) {
        int idx = i*1024 + t;
        buf[idx] = g * (l[i] * inv) + (1.0f - g) * hp[idx];
    }
    __syncthreads();

    float p[8]; float psum = 0.0f;
    #pragma unroll
    for (int i = 0; i < 8; i++) {
        int idx = i*1024 + t;
        float o = s0 * buf[(idx + N - 2) & (N-1)]
                + s1 * buf[(idx + N - 1) & (N-1)]
                + s2 * buf[idx];
        p[i] = __powf(o, gamma);
        psum += p[i];
    }
    float inv2 = 1.0f / bsum1k(psum, red);
    #pragma unroll
    for (int i = 0; i < 8; i++) out_head[(size_t)b*N + i*1024 + t] = p[i] * inv2;
}

// ===========================================================================
// L3: mread REV (R3-proven plain streaming). grid (NCHUNK, B), 256 threads.
// ===========================================================================
__global__ void mread_kernel(const float* __restrict__ Mem,
                             const float* __restrict__ rhead)
{
    int chunk = NCHUNK - 1 - blockIdx.x;     // reversed
    int b     = B - 1 - blockIdx.y;          // reversed
    int t = threadIdx.x;
    int lane8 = t & 7, rowp = t >> 3;
    __shared__ float sdata[256*8];
    float a0=0,a1=0,a2=0,a3=0,a4=0,a5=0,a6=0,a7=0;
    const float* hp = rhead + (size_t)b*N;
    const int ROWS = N / NCHUNK;             // 512
    #pragma unroll 4
    for (int it = 0; it < ROWS/32; it++) {
        int n = chunk*ROWS + it*32 + rowp;
        float r = hp[n];
        const float4* p = (const float4*)(Mem + ((size_t)b*N + n)*M) + lane8*2;
        float4 v0 = p[0], v1 = p[1];
        a0 += r*v0.x; a1 += r*v0.y; a2 += r*v0.z; a3 += r*v0.w;
        a4 += r*v1.x; a5 += r*v1.y; a6 += r*v1.z; a7 += r*v1.w;
    }
    float* s = sdata + t*8;
    s[0]=a0; s[1]=a1; s[2]=a2; s[3]=a3; s[4]=a4; s[5]=a5; s[6]=a6; s[7]=a7;
    __syncthreads();
    if (t < 64) {
        int lg2 = t >> 3, j = t & 7;
        float acc = 0.0f;
        #pragma unroll
        for (int rw = 0; rw < 32; rw++) acc += sdata[((rw<<3) | lg2)*8 + j];
        g_mpart[((size_t)b*NCHUNK + chunk)*M + lg2*8 + j] = acc;
    }
}

// ===========================================================================
// L4: fc — per-batch [reduce partials -> gates fixup -> LSTM -> write ctrl]
// ===========================================================================
__global__ void fc_kernel(const float* __restrict__ W_ih,
                          const float* __restrict__ c,
                          float* __restrict__ out_h, float* __restrict__ out_c,
                          const float* __restrict__ wk_w, const float* __restrict__ wk_b,
                          const float* __restrict__ wc_w, const float* __restrict__ wc_b,
                          const float* __restrict__ ws_w, const float* __restrict__ ws_b,
                          const float* __restrict__ w_w,  const float* __restrict__ w_b)
{
    int b = blockIdx.x, t = threadIdx.x;
    __shared__ float mr[M];
    __shared__ float hs[H];
    __shared__ float sr[256];

    // reduce NCHUNK=16 partial chunks -> M_read[b]
    {
        int m = t & 63, q = t >> 6;          // q = 0..3, 4 chunks each
        float a = 0.0f;
        #pragma unroll
        for (int p = 0; p < 4; p++)
            a += g_mpart[((size_t)b*NCHUNK + q*4 + p)*M + m];
        sr[t] = a;
        __syncthreads();
        if (t < 64) mr[t] = sr[t] + sr[64+t] + sr[128+t] + sr[192+t];
        __syncthreads();
    }

    // gates fixup + LSTM cell: thread handles h = t and t+256
    #pragma unroll
    for (int i = 0; i < 2; i++) {
        int hh = t + i*256;
        float gv[4];
        #pragma unroll
        for (int gg = 0; gg < 4; gg++) {
            int j = gg*H + hh;
            float acc = g_gatesT[(size_t)j*B + b];
            const float4* w4 = (const float4*)(W_ih + (size_t)j*(IN_DIM + M) + IN_DIM);
            #pragma unroll
            for (int q = 0; q < 16; q++) {
                float4 wv = w4[q];
                acc += wv.x*mr[q*4+0] + wv.y*mr[q*4+1] + wv.z*mr[q*4+2] + wv.w*mr[q*4+3];
            }
            gv[gg] = acc;
        }
        float cn = sigf(gv[1]) * c[(size_t)b*H + hh] + sigf(gv[0]) * tanhf(gv[2]);
        float hn = sigf(gv[3]) * tanhf(cn);
        out_c[(size_t)b*H + hh] = cn;
        out_h[(size_t)b*H + hh] = hn;
        hs[hh] = hn;
    }
    __syncthreads();

    // write-controller on h_new (in smem)
    controller_core(b, hs, wk_w, wk_b, wc_w, wc_b, ws_w, ws_b, w_w, w_b);
}

// ===========================================================================
// L7: mout REV (R3-proven plain streaming + stcs). grid (32, B), 256 threads.
// ===========================================================================
__global__ void mout_kernel(const float* __restrict__ Mem,
                            const float* __restrict__ whead,
                            float* __restrict__ outM)
{
    int nblk = 31 - blockIdx.x;              // reversed
    int b    = B - 1 - blockIdx.y;           // reversed
    int t = threadIdx.x;
    __shared__ float es[M], as[M];
    if (t < M) es[t] = g_ea[b*2*M + t];
    else if (t < 2*M) as[t - M] = g_ea[b*2*M + t];
    __syncthreads();
    int lane8 = t & 7, rowp = t >> 3;
    int m0 = lane8 * 8;
    float e0=es[m0],e1=es[m0+1],e2=es[m0+2],e3=es[m0+3];
    float e4=es[m0+4],e5=es[m0+5],e6=es[m0+6],e7=es[m0+7];
    float A0=as[m0],A1=as[m0+1],A2=as[m0+2],A3=as[m0+3];
    float A4=as[m0+4],A5=as[m0+5],A6=as[m0+6],A7=as[m0+7];
    #pragma unroll
    for (int it = 0; it < 8; it++) {
        int n = nblk*256 + it*32 + rowp;
        float w = whead[(size_t)b*N + n];
        size_t off = ((size_t)b*N + n)*M;
        const float4* p = (const float4*)(Mem + off) + lane8*2;
        float4 v0 = p[0], v1 = p[1];
        float4 o0, o1;
        o0.x = v0.x*(1.0f - w*e0) + w*A0;
        o0.y = v0.y*(1.0f - w*e1) + w*A1;
        o0.z = v0.z*(1.0f - w*e2) + w*A2;
        o0.w = v0.w*(1.0f - w*e3) + w*A3;
        o1.x = v1.x*(1.0f - w*e4) + w*A4;
        o1.y = v1.y*(1.0f - w*e5) + w*A5;
        o1.z = v1.z*(1.0f - w*e6) + w*A6;
        o1.w = v1.w*(1.0f - w*e7) + w*A7;
        float4* q = (float4*)(outM + off) + lane8*2;
        __stcs(q,     o0);
        __stcs(q + 1, o1);
    }
}

// ---------------------------------------------------------------------------
extern "C" void kernel_launch(void* const* d_in, const int* in_sizes, int n_in,
                              void* d_out, int out_size)
{
    const float* inp    = (const float*)d_in[0];
    const float* h      = (const float*)d_in[1];
    const float* c      = (const float*)d_in[2];
    const float* rhead  = (const float*)d_in[3];
    const float* whead  = (const float*)d_in[4];
    const float* mem    = (const float*)d_in[5];
    const float* W_ih   = (const float*)d_in[6];
    const float* b_ih   = (const float*)d_in[7];
    const float* W_hh   = (const float*)d_in[8];
    const float* b_hh   = (const float*)d_in[9];
    const float* rk_w   = (const float*)d_in[10];
    const float* rk_b   = (const float*)d_in[11];
    const float* rc_w   = (const float*)d_in[12];
    const float* rc_b   = (const float*)d_in[13];
    const float* rs_w   = (const float*)d_in[14];
    const float* rs_b   = (const float*)d_in[15];
    const float* wk_w   = (const float*)d_in[16];
    const float* wk_b   = (const float*)d_in[17];
    const float* wc_w   = (const float*)d_in[18];
    const float* wc_b   = (const float*)d_in[19];
    const float* ws_w   = (const float*)d_in[20];
    const float* ws_b   = (const float*)d_in[21];
    const float* w_w    = (const float*)d_in[22];
    const float* w_b    = (const float*)d_in[23];

    float* out   = (float*)d_out;
    float* out_h = out;
    float* out_c = out + OUT_C_OFF;
    float* out_r = out + OUT_R_OFF;
    float* out_w = out + OUT_W_OFF;
    float* out_m = out + OUT_M_OFF;

    ctrl_kernel<<<B, 256>>>(h, rk_w, rk_b, rc_w, rc_b, rs_w, rs_b);
    dotg_kernel<<<64 + B*32, 256>>>(mem, inp, h, W_ih, b_ih, W_hh, b_hh);
    address_kernel<<<B, 1024>>>(rhead, out_r);
    mread_kernel<<<dim3(NCHUNK, B), 256>>>(mem, out_r);
    fc_kernel<<<B, 256>>>(W_ih, c, out_h, out_c,
                          wk_w, wk_b, wc_w, wc_b, ws_w, ws_b, w_w, w_b);
    dotw_kernel<<<B*32, 256>>>(mem);
    address_kernel<<<B, 1024>>>(whead, out_w);
    mout_kernel<<<dim3(32, B), 256>>>(mem, out_w, out_m);
}